// round 8
// baseline (speedup 1.0000x reference)
#include <cuda_runtime.h>
#include <cuda_pipeline.h>
#include <cstddef>

// out[b,i,j]: pairwise-sorted, per-column cyclically shifted v (B=8, L=4096, D=1024 fp32).
//   s_j = (j==0) ? 0 : 2*(j-1)   (even)
//   out pair (i,i+1), i even: sort( v[(i-s_j)%L, j], v[(i+1-s_j)%L, j] )
//
// CTA = one column strip (C=32 cols) x TILES=4 consecutive row tiles (R=256).
// Double-buffered cp.async pipeline: band for tile t+1 streams into the other
// smem buffer (pre-shifted per column, predicated 4B LDGSTS) while tile t is
// consumed. Grid is column-strip-fastest so concurrent CTAs collectively read
// full DRAM rows.

namespace {
constexpr int L      = 4096;
constexpr int D      = 1024;
constexpr int C      = 32;     // columns per strip
constexpr int R      = 256;    // rows per tile
constexpr int STRIDE = 33;     // smem row stride (floats) -> conflict-free stores
constexpr int BAND   = R + 64; // band rows per tile (covers max shift spread 62)
constexpr int NT     = 512;
constexpr int TILES  = 4;      // row tiles per CTA
constexpr int BUF_FLOATS = R * STRIDE;                     // 8448
constexpr size_t SMEM_BYTES = 2ull * BUF_FLOATS * sizeof(float);  // 67584
}

__global__ __launch_bounds__(NT, 3)
void swd_kernel(const float* __restrict__ v, float* __restrict__ out) {
    extern __shared__ float smem[];
    float* const buf0 = smem;
    float* const buf1 = smem + BUF_FLOATS;

    const int j0    = blockIdx.x * C;             // column strip (fastest)
    const int ibase = blockIdx.y * (TILES * R);   // first row tile of this CTA
    const int b     = blockIdx.z;

    const int q  = threadIdx.x & 7;   // column quad
    const int tr = threadIdx.x >> 3;  // 0..63
    const int cb = 4 * q;

    const int j_hi     = j0 + C - 1;              // >= 31
    const int shift_hi = 2 * (j_hi - 1);

    const float* __restrict__ vb = v   + (size_t)b * (L * D);
    float*       __restrict__ ob = out + (size_t)b * (L * D);

    // Per-column band offset: off_k = shift_hi - s_{j0+cb+k} in [0,62], even
    int off_[4];
    #pragma unroll
    for (int k = 0; k < 4; k++) {
        int j  = j0 + cb + k;
        int sj = (j == 0) ? 0 : 2 * (j - 1);
        off_[k] = shift_hi - sj;
    }

    // Async-load one tile's band into dstbuf (pre-shifted, predicated).
    auto load_tile = [&](int t, float* dstbuf) {
        const int band_base = ibase + t * R - shift_hi;   // may be negative
        #pragma unroll
        for (int it = 0; it < BAND / 64; it++) {          // 5 iterations
            int rr = it * 64 + tr;                        // band row 0..319
            int g  = (band_base + rr) & (L - 1);
            const float* src = vb + (size_t)g * D + (j0 + cb);
            #pragma unroll
            for (int k = 0; k < 4; k++) {
                int srow = rr - off_[k];
                if ((unsigned)srow < (unsigned)R)
                    __pipeline_memcpy_async(dstbuf + srow * STRIDE + cb + k,
                                            src + k, 4);
            }
        }
        __pipeline_commit();
    };

    load_tile(0, buf0);

    #pragma unroll
    for (int t = 0; t < TILES; t++) {
        // Issue next tile's loads into the other buffer (non-blocking),
        // then wait for this tile's group.
        if (t + 1 < TILES) {
            load_tile(t + 1, ((t + 1) & 1) ? buf1 : buf0);
            __pipeline_wait_prior(1);
        } else {
            __pipeline_wait_prior(0);
        }
        __syncthreads();   // all threads' tile-t copies visible

        const float* s_ = (t & 1) ? buf1 : buf0;
        const int i0 = ibase + t * R;

        #pragma unroll
        for (int it = 0; it < 2; it++) {
            int p = it * 64 + tr;                          // pair 0..127
            const float* base = s_ + (2 * p) * STRIDE + cb;    // even offset
            float2 a01 = *reinterpret_cast<const float2*>(base);
            float2 a23 = *reinterpret_cast<const float2*>(base + 2);
            // Row b via even offset base+STRIDE-1; stray lanes discarded.
            const float* r1m = base + (STRIDE - 1);
            float2 t0 = *reinterpret_cast<const float2*>(r1m);
            float2 t1 = *reinterpret_cast<const float2*>(r1m + 2);
            float2 t2 = *reinterpret_cast<const float2*>(r1m + 4);
            float b0 = t0.y, b1 = t1.x, b2 = t1.y, b3 = t2.x;
            float4 lo, hi;
            lo.x = fminf(a01.x, b0); hi.x = fmaxf(a01.x, b0);
            lo.y = fminf(a01.y, b1); hi.y = fmaxf(a01.y, b1);
            lo.z = fminf(a23.x, b2); hi.z = fmaxf(a23.x, b2);
            lo.w = fminf(a23.y, b3); hi.w = fmaxf(a23.y, b3);
            float* dst = ob + (size_t)(i0 + 2 * p) * D + (j0 + cb);
            __stcs(reinterpret_cast<float4*>(dst),     lo);
            __stcs(reinterpret_cast<float4*>(dst + D), hi);
        }
        __syncthreads();   // consume done before this buffer is overwritten
    }
}

extern "C" void kernel_launch(void* const* d_in, const int* in_sizes, int n_in,
                              void* d_out, int out_size) {
    const float* v   = (const float*)d_in[0];
    float*       out = (float*)d_out;
    const int B = in_sizes[0] / (L * D);

    cudaFuncSetAttribute(swd_kernel,
                         cudaFuncAttributeMaxDynamicSharedMemorySize,
                         (int)SMEM_BYTES);

    dim3 grid(D / C, L / (R * TILES), B);   // 32 x 4 x B, column-strip fastest
    swd_kernel<<<grid, NT, SMEM_BYTES>>>(v, out);
}

// round 10
// speedup vs baseline: 1.4119x; 1.4119x over previous
#include <cuda_runtime.h>
#include <cstddef>

// out[b,i,j]: pairwise-sorted, per-column cyclically shifted v (B=8, L=4096, D=1024 fp32).
//   s_j = (j==0) ? 0 : 2*(j-1)   (always even)
//   out pair (i, i+1), i even:  sort( v[(i-s_j)%L, j], v[(i+1-s_j)%L, j] )
//
// Tile: R=256 output rows x C=32 cols per CTA.  Grid: column-strip fastest
// (blockIdx.x = strip) so co-resident CTAs collectively read full DRAM rows.
// Smem band is PRE-SHIFTED per column with a 64-row margin on both sides:
//   store row for column j at band row rr is  rr - off_j + PAD  in [2, 383]
//   -> no predication in the load loop (5x LDG.128 + 20x STS.32, batched).
// Load  STS bank = rr+12q+3k -> 32 distinct -> conflict-free.
// Consume: 5x LDS.64 all at even float offsets (row-b read via even offset
//   base+STRIDE-1, stray lanes discarded), bank-pair (p+2q) mod 16 ->
//   conflict-free; then min/max + 2x streaming STG.128.

namespace {
constexpr int L      = 4096;
constexpr int D      = 1024;
constexpr int C      = 32;     // columns per tile
constexpr int R      = 256;    // output rows per tile
constexpr int STRIDE = 33;     // smem row stride (floats)
constexpr int PAD    = 64;     // margin rows
constexpr int ROWS   = R + 2 * PAD;   // 384
constexpr int BAND   = R + 64; // global rows loaded per tile
constexpr int NT     = 512;
constexpr size_t SMEM_BYTES = (size_t)ROWS * STRIDE * sizeof(float);  // 50688
}

__global__ __launch_bounds__(NT, 4)
void swd_kernel(const float* __restrict__ v, float* __restrict__ out) {
    extern __shared__ float s[];

    const int j0 = blockIdx.x * C;    // column strip (fastest)
    const int i0 = blockIdx.y * R;    // output row tile base (even)
    const int b  = blockIdx.z;

    const int q  = threadIdx.x & 7;   // column quad (4 cols)
    const int tr = threadIdx.x >> 3;  // 0..63

    const int j_hi      = j0 + C - 1;           // >= 31
    const int shift_hi  = 2 * (j_hi - 1);
    const int band_base = i0 - shift_hi;        // may be negative (mask wraps)

    const float* __restrict__ vb = v   + (size_t)b * (L * D);
    float*       __restrict__ ob = out + (size_t)b * (L * D);

    const int cb = 4 * q;

    // Per-column smem float offset: (PAD - off_k)*STRIDE + cb + k, off in [0,62]
    int sofs[4];
    #pragma unroll
    for (int k = 0; k < 4; k++) {
        int j   = j0 + cb + k;
        int sj  = (j == 0) ? 0 : 2 * (j - 1);
        sofs[k] = (PAD - (shift_hi - sj)) * STRIDE + cb + k;
    }

    // ---- Load band: 5x LDG.128 (batched, high MLP) + 20x unpredicated STS ----
    float4 val[BAND / 64];
    #pragma unroll
    for (int it = 0; it < BAND / 64; it++) {   // 5 independent loads
        int rr = it * 64 + tr;                 // band row 0..319
        int g  = (band_base + rr) & (L - 1);
        val[it] = *reinterpret_cast<const float4*>(vb + (size_t)g * D + (j0 + cb));
    }
    #pragma unroll
    for (int it = 0; it < BAND / 64; it++) {
        float* srow = s + (it * 64 + tr) * STRIDE;
        srow[sofs[0]] = val[it].x;
        srow[sofs[1]] = val[it].y;
        srow[sofs[2]] = val[it].z;
        srow[sofs[3]] = val[it].w;
    }
    __syncthreads();

    // ---- Consume: 5x LDS.64 + min/max + 2x STG.128 ----
    #pragma unroll
    for (int it = 0; it < (R / 2) * 8 / NT; it++) {   // 2 iterations
        int p = it * 64 + tr;                          // pair 0..127
        const float* base = s + (PAD + 2 * p) * STRIDE + cb;   // even offset
        float2 a01 = *reinterpret_cast<const float2*>(base);
        float2 a23 = *reinterpret_cast<const float2*>(base + 2);
        // Row b starts at base + STRIDE (odd). Read from even offset
        // base + STRIDE - 1; stray extracted lanes are in-bounds junk.
        const float* r1m = base + (STRIDE - 1);
        float2 t0 = *reinterpret_cast<const float2*>(r1m);       // {junk, b0}
        float2 t1 = *reinterpret_cast<const float2*>(r1m + 2);   // {b1, b2}
        float2 t2 = *reinterpret_cast<const float2*>(r1m + 4);   // {b3, junk}
        float b0 = t0.y, b1 = t1.x, b2 = t1.y, b3 = t2.x;
        float4 lo, hi;
        lo.x = fminf(a01.x, b0); hi.x = fmaxf(a01.x, b0);
        lo.y = fminf(a01.y, b1); hi.y = fmaxf(a01.y, b1);
        lo.z = fminf(a23.x, b2); hi.z = fmaxf(a23.x, b2);
        lo.w = fminf(a23.y, b3); hi.w = fmaxf(a23.y, b3);
        float* dst = ob + (size_t)(i0 + 2 * p) * D + (j0 + cb);
        __stcs(reinterpret_cast<float4*>(dst),     lo);
        __stcs(reinterpret_cast<float4*>(dst + D), hi);
    }
}

extern "C" void kernel_launch(void* const* d_in, const int* in_sizes, int n_in,
                              void* d_out, int out_size) {
    const float* v   = (const float*)d_in[0];
    float*       out = (float*)d_out;
    const int B = in_sizes[0] / (L * D);

    cudaFuncSetAttribute(swd_kernel,
                         cudaFuncAttributeMaxDynamicSharedMemorySize,
                         (int)SMEM_BYTES);

    dim3 grid(D / C, L / R, B);   // 32 x 16 x B, column-strip fastest
    swd_kernel<<<grid, NT, SMEM_BYTES>>>(v, out);
}

// round 11
// speedup vs baseline: 1.4144x; 1.0017x over previous
#include <cuda_runtime.h>
#include <cstddef>

// out[b,i,j]: pairwise-sorted, per-column cyclically shifted v (B=8, L=4096, D=1024 fp32).
//   s_j = (j==0) ? 0 : 2*(j-1)   (always even)
//   out pair (i, i+1), i even:  sort( v[(i-s_j)%L, j], v[(i+1-s_j)%L, j] )
//
// Tile: R=256 output rows x C=32 cols per CTA.  Grid: column-strip fastest
// (blockIdx.x = strip) so co-resident CTAs collectively read full DRAM rows.
// Smem band is PRE-SHIFTED per column with a 64-row margin on both sides:
//   store row for column j at band row rr is  rr - off_j + PAD  in [2, 383]
//   -> no predication in the load loop (5x LDG.128 + 20x STS.32, batched).
// Load  STS bank = rr+12q+3k -> 32 distinct -> conflict-free.
// Consume: 5x LDS.64 all at even float offsets (row-b read via even offset
//   base+STRIDE-1, stray lanes discarded), bank-pair (p+2q) mod 16 ->
//   conflict-free; then min/max + 2x streaming STG.128.

namespace {
constexpr int L      = 4096;
constexpr int D      = 1024;
constexpr int C      = 32;     // columns per tile
constexpr int R      = 256;    // output rows per tile
constexpr int STRIDE = 33;     // smem row stride (floats)
constexpr int PAD    = 64;     // margin rows
constexpr int ROWS   = R + 2 * PAD;   // 384
constexpr int BAND   = R + 64; // global rows loaded per tile
constexpr int NT     = 512;
constexpr size_t SMEM_BYTES = (size_t)ROWS * STRIDE * sizeof(float);  // 50688
}

__global__ __launch_bounds__(NT, 4)
void swd_kernel(const float* __restrict__ v, float* __restrict__ out) {
    extern __shared__ float s[];

    const int j0 = blockIdx.x * C;    // column strip (fastest)
    const int i0 = blockIdx.y * R;    // output row tile base (even)
    const int b  = blockIdx.z;

    const int q  = threadIdx.x & 7;   // column quad (4 cols)
    const int tr = threadIdx.x >> 3;  // 0..63

    const int j_hi      = j0 + C - 1;           // >= 31
    const int shift_hi  = 2 * (j_hi - 1);
    const int band_base = i0 - shift_hi;        // may be negative (mask wraps)

    const float* __restrict__ vb = v   + (size_t)b * (L * D);
    float*       __restrict__ ob = out + (size_t)b * (L * D);

    const int cb = 4 * q;

    // Per-column smem float offset: (PAD - off_k)*STRIDE + cb + k, off in [0,62]
    int sofs[4];
    #pragma unroll
    for (int k = 0; k < 4; k++) {
        int j   = j0 + cb + k;
        int sj  = (j == 0) ? 0 : 2 * (j - 1);
        sofs[k] = (PAD - (shift_hi - sj)) * STRIDE + cb + k;
    }

    // ---- Load band: 5x LDG.128 (batched, high MLP) + 20x unpredicated STS ----
    float4 val[BAND / 64];
    #pragma unroll
    for (int it = 0; it < BAND / 64; it++) {   // 5 independent loads
        int rr = it * 64 + tr;                 // band row 0..319
        int g  = (band_base + rr) & (L - 1);
        val[it] = *reinterpret_cast<const float4*>(vb + (size_t)g * D + (j0 + cb));
    }
    #pragma unroll
    for (int it = 0; it < BAND / 64; it++) {
        float* srow = s + (it * 64 + tr) * STRIDE;
        srow[sofs[0]] = val[it].x;
        srow[sofs[1]] = val[it].y;
        srow[sofs[2]] = val[it].z;
        srow[sofs[3]] = val[it].w;
    }
    __syncthreads();

    // ---- Consume: 5x LDS.64 + min/max + 2x STG.128 ----
    #pragma unroll
    for (int it = 0; it < (R / 2) * 8 / NT; it++) {   // 2 iterations
        int p = it * 64 + tr;                          // pair 0..127
        const float* base = s + (PAD + 2 * p) * STRIDE + cb;   // even offset
        float2 a01 = *reinterpret_cast<const float2*>(base);
        float2 a23 = *reinterpret_cast<const float2*>(base + 2);
        // Row b starts at base + STRIDE (odd). Read from even offset
        // base + STRIDE - 1; stray extracted lanes are in-bounds junk.
        const float* r1m = base + (STRIDE - 1);
        float2 t0 = *reinterpret_cast<const float2*>(r1m);       // {junk, b0}
        float2 t1 = *reinterpret_cast<const float2*>(r1m + 2);   // {b1, b2}
        float2 t2 = *reinterpret_cast<const float2*>(r1m + 4);   // {b3, junk}
        float b0 = t0.y, b1 = t1.x, b2 = t1.y, b3 = t2.x;
        float4 lo, hi;
        lo.x = fminf(a01.x, b0); hi.x = fmaxf(a01.x, b0);
        lo.y = fminf(a01.y, b1); hi.y = fmaxf(a01.y, b1);
        lo.z = fminf(a23.x, b2); hi.z = fmaxf(a23.x, b2);
        lo.w = fminf(a23.y, b3); hi.w = fmaxf(a23.y, b3);
        float* dst = ob + (size_t)(i0 + 2 * p) * D + (j0 + cb);
        __stcs(reinterpret_cast<float4*>(dst),     lo);
        __stcs(reinterpret_cast<float4*>(dst + D), hi);
    }
}

extern "C" void kernel_launch(void* const* d_in, const int* in_sizes, int n_in,
                              void* d_out, int out_size) {
    const float* v   = (const float*)d_in[0];
    float*       out = (float*)d_out;
    const int B = in_sizes[0] / (L * D);

    cudaFuncSetAttribute(swd_kernel,
                         cudaFuncAttributeMaxDynamicSharedMemorySize,
                         (int)SMEM_BYTES);

    dim3 grid(D / C, L / R, B);   // 32 x 16 x B, column-strip fastest
    swd_kernel<<<grid, NT, SMEM_BYTES>>>(v, out);
}